// round 6
// baseline (speedup 1.0000x reference)
#include <cuda_runtime.h>

#define NDIM 1000
#define PDIM 50000
#define ZDIM 10
#define LDIM 5

#define NSPLIT 8
#define NCHUNK (NDIM / NSPLIT)                        // 125
#define K1_THREADS 256
#define K1_PTILE (K1_THREADS * 4)                     // 1024
#define K1_PTILES ((PDIM + K1_PTILE - 1) / K1_PTILE)  // 49
#define K1_MAIN (K1_PTILES * NSPLIT)                  // 392

#define K2_BLOCKS 98
#define K2_THREADS 256
#define NSTEPS (ZDIM * LDIM)                          // 50

#define OUT_VW_OFF (LDIM * ZDIM * PDIM)               // 250000
#define OUT_AL_OFF (OUT_VW_OFF + LDIM * ZDIM)         // 250050

// Static device scratch (no runtime allocation allowed)
__device__ __align__(16) float g_ztrp[NSPLIT][ZDIM][PDIM];   // 16 MB partials
__device__ float g_mzz[ZDIM * ZDIM];
// Per-step per-block packed partial: hi32 = m (f32 bits), lo32 = s (f32 bits).
// s >= 1 always, so a nonzero word == published (payload is its own flag).
// Zeroed by k1 aux block each launch.
__device__ __align__(16) unsigned long long g_slot[NSTEPS][K2_BLOCKS];

__device__ __forceinline__ void st_release_u64(unsigned long long* p, unsigned long long v) {
    asm volatile("st.release.gpu.global.u64 [%0], %1;" :: "l"(p), "l"(v) : "memory");
}
__device__ __forceinline__ unsigned long long ld_acq_u64(const unsigned long long* p) {
    unsigned long long v;
    asm volatile("ld.acquire.gpu.global.u64 %0, [%1];" : "=l"(v) : "l"(p) : "memory");
    return v;
}

// one-exp online-softmax combine: (m,s) <- comb((m,s),(mo,so))
// nm = max(m,mo); one rescale factor is always exp(0)=1.
__device__ __forceinline__ void comb(float& m, float& s, float mo, float so) {
    float d = m - mo;
    float e = __expf(-fabsf(d));
    bool ge = (d >= 0.f);
    s = ge ? fmaf(so, e, s) : fmaf(s, e, so);
    m = ge ? m : mo;
}

// ---------------------------------------------------------------------------
// Kernel 1: ZtR partials (ZtR[k,p] = sum_n mean_z[n,k]*data[n,p]) split over
// NSPLIT n-chunks, plus mean_zz, vw output, and slot zeroing.
// ---------------------------------------------------------------------------
__global__ __launch_bounds__(K1_THREADS)
void k1_ztr(const float* __restrict__ data,
            const float* __restrict__ mean_z,
            const float* __restrict__ var_z,
            const float* __restrict__ tau_0,
            const float* __restrict__ tau_p,
            float* __restrict__ out_vw)
{
    const int b = blockIdx.x;
    const int tid = threadIdx.x;

    if (b == K1_MAIN) {
        // Aux block: zero slots, compute mean_zz = Z^T Z + N*var_z, write vw.
        unsigned long long* sl = &g_slot[0][0];
        for (int i = tid; i < NSTEPS * K2_BLOCKS; i += K1_THREADS) sl[i] = 0ull;
        __shared__ float s_mzz[ZDIM * ZDIM];
        if (tid < ZDIM * ZDIM) {
            int i = tid / ZDIM, j = tid % ZDIM;
            float s = 0.f;
            for (int n = 0; n < NDIM; n++)
                s += mean_z[n * ZDIM + i] * mean_z[n * ZDIM + j];
            s += (float)NDIM * var_z[i * ZDIM + j];
            s_mzz[tid] = s;
            g_mzz[tid] = s;
        }
        __syncthreads();
        if (tid < LDIM * ZDIM) {
            int l = tid / ZDIM, k = tid % ZDIM;
            float tau = tau_p[0];
            out_vw[tid] = 1.0f / (tau * s_mzz[k * ZDIM + k] + tau_0[l * ZDIM + k]);
        }
        return;
    }

    const int pt = b % K1_PTILES;
    const int c  = b / K1_PTILES;

    // mean_z chunk in shared, rows padded to 12 floats for float4 reads.
    __shared__ __align__(16) float s_z[NCHUNK][12];
    for (int i = tid; i < NCHUNK * ZDIM; i += K1_THREADS) {
        int n = i / ZDIM, kk = i % ZDIM;
        s_z[n][kk] = mean_z[(c * NCHUNK + n) * ZDIM + kk];
    }
    __syncthreads();

    const int p0 = pt * K1_PTILE + tid * 4;
    if (p0 >= PDIM) return;   // P % 4 == 0 -> p0..p0+3 all valid when p0 < P

    float4 acc[ZDIM];
#pragma unroll
    for (int k = 0; k < ZDIM; k++) acc[k] = make_float4(0.f, 0.f, 0.f, 0.f);

    const float* dptr = data + (size_t)c * NCHUNK * PDIM + p0;
#pragma unroll 2
    for (int n = 0; n < NCHUNK; n++) {
        float4 d = *reinterpret_cast<const float4*>(dptr + (size_t)n * PDIM);
        const float4* zr = reinterpret_cast<const float4*>(s_z[n]);
        float4 z0 = zr[0], z1 = zr[1], z2 = zr[2];
        float zk[ZDIM] = {z0.x, z0.y, z0.z, z0.w, z1.x, z1.y, z1.z, z1.w, z2.x, z2.y};
#pragma unroll
        for (int k = 0; k < ZDIM; k++) {
            acc[k].x = fmaf(zk[k], d.x, acc[k].x);
            acc[k].y = fmaf(zk[k], d.y, acc[k].y);
            acc[k].z = fmaf(zk[k], d.z, acc[k].z);
            acc[k].w = fmaf(zk[k], d.w, acc[k].w);
        }
    }
#pragma unroll
    for (int k = 0; k < ZDIM; k++)
        *reinterpret_cast<float4*>(&g_ztrp[c][k][p0]) = acc[k];
}

// ---------------------------------------------------------------------------
// Kernel 2: persistent serial coordinate-descent sweep. 98 co-resident CTAs,
// each thread owns 2 p-columns. R3 topology (only warp 0 touches the global
// rendezvous; warps 1-7 park at __syncthreads), but counter-free: packed u64
// payload-as-flag slots merge detect + data fetch into one L2 round.
// ---------------------------------------------------------------------------
__global__ __launch_bounds__(K2_THREADS)
void k2_loop(const float* __restrict__ mw_in,
             const float* __restrict__ al_in,
             const float* __restrict__ pi,
             const float* __restrict__ tau_0,
             const float* __restrict__ tau_p,
             float* __restrict__ out)
{
    const int tid  = threadIdx.x;
    const int b    = blockIdx.x;
    const int wid  = tid >> 5;
    const int lane = tid & 31;

    float* out_mw = out;
    float* out_al = out + OUT_AL_OFF;

    __shared__ float s_mzz[ZDIM * ZDIM];
    __shared__ float s_t0[LDIM * ZDIM];
    __shared__ float2 s_red[8];
    __shared__ float s_ms[2];

    if (tid < ZDIM * ZDIM) s_mzz[tid] = g_mzz[tid];
    if (tid < LDIM * ZDIM) s_t0[tid] = tau_0[tid];
    const float tau = tau_p[0];

    const int p0 = b * (K2_THREADS * 2) + tid;     // always < PDIM (max 49919)
    const int p1 = p0 + K2_THREADS;
    const bool v1 = (p1 < PDIM);

    // Per-thread register state: W columns, ZtR columns, log(pi) for its two p's.
    float W[ZDIM][2], Zt[ZDIM][2], lpi[ZDIM][2];
#pragma unroll
    for (int k = 0; k < ZDIM; k++) {
        {
            float zt = 0.f;
#pragma unroll
            for (int c = 0; c < NSPLIT; c++) zt += g_ztrp[c][k][p0];
            float w = 0.f;
#pragma unroll
            for (int l = 0; l < LDIM; l++) {
                size_t idx = (size_t)(l * ZDIM + k) * PDIM + p0;
                w = fmaf(mw_in[idx], al_in[idx], w);
            }
            Zt[k][0] = zt; W[k][0] = w;
            lpi[k][0] = __logf(pi[(size_t)k * PDIM + p0]);
        }
        if (v1) {
            float zt = 0.f;
#pragma unroll
            for (int c = 0; c < NSPLIT; c++) zt += g_ztrp[c][k][p1];
            float w = 0.f;
#pragma unroll
            for (int l = 0; l < LDIM; l++) {
                size_t idx = (size_t)(l * ZDIM + k) * PDIM + p1;
                w = fmaf(mw_in[idx], al_in[idx], w);
            }
            Zt[k][1] = zt; W[k][1] = w;
            lpi[k][1] = __logf(pi[(size_t)k * PDIM + p1]);
        } else { Zt[k][1] = 0.f; W[k][1] = 0.f; lpi[k][1] = 0.f; }
    }
    __syncthreads();

#pragma unroll
    for (int k = 0; k < ZDIM; k++) {
        const float Ezz = s_mzz[k * ZDIM + k];
        float Rt[2], Wk[2];
#pragma unroll
        for (int e = 0; e < 2; e++) {
            float s = Zt[k][e];
#pragma unroll
            for (int j = 0; j < ZDIM; j++)
                s -= s_mzz[k * ZDIM + j] * W[j][e];
            Rt[e] = s + Ezz * W[k][e];            // = ZtR[k] - sum_{j!=k} mzz[k,j]*W[j]
            Wk[e] = W[k][e];
        }

        // preload mw*al products for l=0 of this k
        float pw0, pw1;
        {
            size_t idx = (size_t)k * PDIM + p0;
            pw0 = mw_in[idx] * al_in[idx];
            pw1 = v1 ? mw_in[idx + K2_THREADS] * al_in[idx + K2_THREADS] : 0.f;
        }

        for (int l = 0; l < LDIM; l++) {
            const int step = k * LDIM + l;

            // issue raw loads for next l early (consumed at loop end)
            const int ln = (l + 1 < LDIM) ? l + 1 : l;
            const size_t nidx = (size_t)(ln * ZDIM + k) * PDIM + p0;
            float nm0 = mw_in[nidx], na0 = al_in[nidx];
            float nm1 = 0.f, na1 = 0.f;
            if (v1) { nm1 = mw_in[nidx + K2_THREADS]; na1 = al_in[nidx + K2_THREADS]; }

            const float t0    = s_t0[l * ZDIM + k];
            const float u_var = 1.f / (tau * Ezz + t0);
            const float s2    = 1.f / (Ezz * tau);
            const float s0inv = 1.f / t0;
            // logit = log(pi) + C2*r^2  (constant part of log_bf cancels in softmax)
            const float C2 = 0.5f * (tau / Ezz) * (s0inv / (s2 + s0inv));

            float Wkl0 = Wk[0] - pw0;
            float r0   = Rt[0] - Ezz * Wkl0;
            float lg0  = fmaf(C2 * r0, r0, lpi[k][0]);
            float Wkl1, r1, lg1;
            if (v1) {
                Wkl1 = Wk[1] - pw1;
                r1   = Rt[1] - Ezz * Wkl1;
                lg1  = fmaf(C2 * r1, r1, lpi[k][1]);
            } else { Wkl1 = 0.f; r1 = 0.f; lg1 = -1e30f; }

            // ---- warp-level online softmax reduce (m, s) ----
            float m = fmaxf(lg0, lg1);
            float s = __expf(lg0 - m) + __expf(lg1 - m);
#pragma unroll
            for (int o = 16; o > 0; o >>= 1) {
                float mo = __shfl_xor_sync(0xffffffffu, m, o);
                float so = __shfl_xor_sync(0xffffffffu, s, o);
                comb(m, s, mo, so);
            }
            if (lane == 0) s_red[wid] = make_float2(m, s);
            __syncthreads();

            if (wid == 0) {
                // block-level reduce over 8 warp results (lanes >= 8 neutral)
                float2 wv = (lane < 8) ? s_red[lane] : make_float2(-1e30f, 0.f);
                float mb = wv.x, sb = wv.y;
#pragma unroll
                for (int o = 4; o > 0; o >>= 1) {
                    float mo = __shfl_xor_sync(0xffffffffu, mb, o);
                    float so = __shfl_xor_sync(0xffffffffu, sb, o);
                    comb(mb, sb, mo, so);
                }
                if (lane == 0) {
                    unsigned long long pv =
                        ((unsigned long long)__float_as_uint(mb) << 32) |
                        (unsigned long long)__float_as_uint(sb);
                    st_release_u64(&g_slot[step][b], pv);   // s>=1 -> word nonzero
                }

                // ---- warp 0 only: poll-with-data (payload is its own flag) ----
                const unsigned long long* slots = &g_slot[step][0];
                const bool a3 = (lane + 96 < K2_BLOCKS);   // lanes 0,1
                // issue all four loads back-to-back (parallel L2 round trips)
                unsigned long long v0g = ld_acq_u64(slots + lane);
                unsigned long long v1g = ld_acq_u64(slots + lane + 32);
                unsigned long long v2g = ld_acq_u64(slots + lane + 64);
                unsigned long long v3g = a3 ? ld_acq_u64(slots + lane + 96) : 0ull;
                // refill stragglers only (proven R2 per-slot spin shape)
                while ((unsigned)v0g == 0u) v0g = ld_acq_u64(slots + lane);
                while ((unsigned)v1g == 0u) v1g = ld_acq_u64(slots + lane + 32);
                while ((unsigned)v2g == 0u) v2g = ld_acq_u64(slots + lane + 64);
                if (a3) while ((unsigned)v3g == 0u) v3g = ld_acq_u64(slots + lane + 96);

                float ma = __uint_as_float((unsigned)(v0g >> 32));
                float sa = __uint_as_float((unsigned)v0g);
                {
                    float m1g = __uint_as_float((unsigned)(v1g >> 32));
                    float s1g = __uint_as_float((unsigned)v1g);
                    comb(ma, sa, m1g, s1g);
                    float mc = __uint_as_float((unsigned)(v2g >> 32));
                    float sc = __uint_as_float((unsigned)v2g);
                    float m3g = a3 ? __uint_as_float((unsigned)(v3g >> 32)) : -1e30f;
                    float s3g = a3 ? __uint_as_float((unsigned)v3g) : 0.f;
                    comb(mc, sc, m3g, s3g);
                    comb(ma, sa, mc, sc);
                }
#pragma unroll
                for (int o = 16; o > 0; o >>= 1) {
                    float mo = __shfl_xor_sync(0xffffffffu, ma, o);
                    float so = __shfl_xor_sync(0xffffffffu, sa, o);
                    comb(ma, sa, mo, so);
                }
                if (lane == 0) { s_ms[0] = ma; s_ms[1] = sa; }
            }
            __syncthreads();
            const float gm = s_ms[0];
            const float gs = s_ms[1];

            // ---- normalize, update Wk, store outputs ----
            {
                float a  = __expf(lg0 - gm) / gs;
                float um = tau * u_var * r0;
                Wk[0] = Wkl0 + um * a;
                size_t idx = (size_t)(l * ZDIM + k) * PDIM + p0;
                out_mw[idx] = um;
                out_al[idx] = a;
            }
            if (v1) {
                float a  = __expf(lg1 - gm) / gs;
                float um = tau * u_var * r1;
                Wk[1] = Wkl1 + um * a;
                size_t idx = (size_t)(l * ZDIM + k) * PDIM + p1;
                out_mw[idx] = um;
                out_al[idx] = a;
            }

            // rotate prefetched products into place for next l
            pw0 = nm0 * na0;
            pw1 = nm1 * na1;
        }
        W[k][0] = Wk[0];
        W[k][1] = Wk[1];
    }
}

// ---------------------------------------------------------------------------
extern "C" void kernel_launch(void* const* d_in, const int* in_sizes, int n_in,
                              void* d_out, int out_size)
{
    (void)in_sizes; (void)n_in; (void)out_size;
    const float* data   = (const float*)d_in[0];
    const float* mean_z = (const float*)d_in[1];
    const float* var_z  = (const float*)d_in[2];
    const float* mean_w = (const float*)d_in[3];
    // d_in[4] = var_w (unused: vw output fully overwritten)
    const float* alpha  = (const float*)d_in[5];
    const float* tau_0  = (const float*)d_in[6];
    const float* pi     = (const float*)d_in[7];
    const float* tau    = (const float*)d_in[8];
    float* out = (float*)d_out;

    k1_ztr<<<K1_MAIN + 1, K1_THREADS>>>(data, mean_z, var_z, tau_0, tau,
                                        out + OUT_VW_OFF);
    k2_loop<<<K2_BLOCKS, K2_THREADS>>>(mean_w, alpha, pi, tau_0, tau, out);
}

// round 7
// speedup vs baseline: 1.5844x; 1.5844x over previous
#include <cuda_runtime.h>

#define NDIM 1000
#define PDIM 50000
#define ZDIM 10
#define LDIM 5

#define NSPLIT 8
#define NCHUNK (NDIM / NSPLIT)                        // 125
#define K1_THREADS 256
#define K1_PTILE (K1_THREADS * 4)                     // 1024
#define K1_PTILES ((PDIM + K1_PTILE - 1) / K1_PTILE)  // 49
#define K1_MAIN (K1_PTILES * NSPLIT)                  // 392

#define K2_BLOCKS 49
#define K2_THREADS 512
#define K2_WARPS (K2_THREADS / 32)                    // 16
#define NSTEPS (ZDIM * LDIM)                          // 50

#define OUT_VW_OFF (LDIM * ZDIM * PDIM)               // 250000
#define OUT_AL_OFF (OUT_VW_OFF + LDIM * ZDIM)         // 250050

// Static device scratch (no runtime allocation allowed)
__device__ __align__(16) float g_ztrp[NSPLIT][ZDIM][PDIM];   // 16 MB partials
__device__ float g_mzz[ZDIM * ZDIM];
__device__ __align__(128) float2 g_part[NSTEPS][64];         // per-step (m, s) per block
__device__ int g_cnt[NSTEPS];                                // per-step arrival counters

// ---- R3-proven rendezvous primitives ----
__device__ __forceinline__ void publish(float2* slot, int* cnt, float m, float s) {
    asm volatile("st.global.v2.f32 [%0], {%1, %2};" :: "l"(slot), "f"(m), "f"(s) : "memory");
    // release-ordering: the v2 store is visible at gpu scope before the increment
    asm volatile("red.release.gpu.global.add.u32 [%0], 1;" :: "l"(cnt) : "memory");
}
__device__ __forceinline__ unsigned ld_acquire_u32(const int* p) {
    unsigned v;
    asm volatile("ld.acquire.gpu.global.u32 %0, [%1];" : "=r"(v) : "l"(p) : "memory");
    return v;
}

// one-exp online-softmax combine: (m,s) <- comb((m,s),(mo,so))
// nm = max(m,mo); one rescale factor is always exp(0)=1.
__device__ __forceinline__ void comb(float& m, float& s, float mo, float so) {
    float d = m - mo;
    float e = __expf(-fabsf(d));
    bool ge = (d >= 0.f);
    s = ge ? fmaf(so, e, s) : fmaf(s, e, so);
    m = ge ? m : mo;
}

// ---------------------------------------------------------------------------
// Kernel 1: ZtR partials (ZtR[k,p] = sum_n mean_z[n,k]*data[n,p]) split over
// NSPLIT n-chunks, plus mean_zz, vw output, and counter reset.
// ---------------------------------------------------------------------------
__global__ __launch_bounds__(K1_THREADS)
void k1_ztr(const float* __restrict__ data,
            const float* __restrict__ mean_z,
            const float* __restrict__ var_z,
            const float* __restrict__ tau_0,
            const float* __restrict__ tau_p,
            float* __restrict__ out_vw)
{
    const int b = blockIdx.x;
    const int tid = threadIdx.x;

    if (b == K1_MAIN) {
        // Aux block: reset counters, compute mean_zz = Z^T Z + N*var_z, write vw.
        if (tid < NSTEPS) g_cnt[tid] = 0;
        __shared__ float s_mzz[ZDIM * ZDIM];
        if (tid < ZDIM * ZDIM) {
            int i = tid / ZDIM, j = tid % ZDIM;
            float s = 0.f;
            for (int n = 0; n < NDIM; n++)
                s += mean_z[n * ZDIM + i] * mean_z[n * ZDIM + j];
            s += (float)NDIM * var_z[i * ZDIM + j];
            s_mzz[tid] = s;
            g_mzz[tid] = s;
        }
        __syncthreads();
        if (tid < LDIM * ZDIM) {
            int l = tid / ZDIM, k = tid % ZDIM;
            float tau = tau_p[0];
            out_vw[tid] = 1.0f / (tau * s_mzz[k * ZDIM + k] + tau_0[l * ZDIM + k]);
        }
        return;
    }

    const int pt = b % K1_PTILES;
    const int c  = b / K1_PTILES;

    // mean_z chunk in shared, rows padded to 12 floats for float4 reads.
    __shared__ __align__(16) float s_z[NCHUNK][12];
    for (int i = tid; i < NCHUNK * ZDIM; i += K1_THREADS) {
        int n = i / ZDIM, kk = i % ZDIM;
        s_z[n][kk] = mean_z[(c * NCHUNK + n) * ZDIM + kk];
    }
    __syncthreads();

    const int p0 = pt * K1_PTILE + tid * 4;
    if (p0 >= PDIM) return;   // P % 4 == 0 -> p0..p0+3 all valid when p0 < P

    float4 acc[ZDIM];
#pragma unroll
    for (int k = 0; k < ZDIM; k++) acc[k] = make_float4(0.f, 0.f, 0.f, 0.f);

    const float* dptr = data + (size_t)c * NCHUNK * PDIM + p0;
#pragma unroll 4
    for (int n = 0; n < NCHUNK; n++) {
        float4 d = *reinterpret_cast<const float4*>(dptr + (size_t)n * PDIM);
        const float4* zr = reinterpret_cast<const float4*>(s_z[n]);
        float4 z0 = zr[0], z1 = zr[1], z2 = zr[2];
        float zk[ZDIM] = {z0.x, z0.y, z0.z, z0.w, z1.x, z1.y, z1.z, z1.w, z2.x, z2.y};
#pragma unroll
        for (int k = 0; k < ZDIM; k++) {
            acc[k].x = fmaf(zk[k], d.x, acc[k].x);
            acc[k].y = fmaf(zk[k], d.y, acc[k].y);
            acc[k].z = fmaf(zk[k], d.z, acc[k].z);
            acc[k].w = fmaf(zk[k], d.w, acc[k].w);
        }
    }
#pragma unroll
    for (int k = 0; k < ZDIM; k++)
        *reinterpret_cast<float4*>(&g_ztrp[c][k][p0]) = acc[k];
}

// ---------------------------------------------------------------------------
// Kernel 2: persistent serial coordinate-descent sweep. 49 co-resident CTAs
// of 512 threads, each thread owns 2 p-columns. R3-shape rendezvous: counter
// RED + lane0 acquire-poll + parallel .cg partial reads.
// ---------------------------------------------------------------------------
__global__ __launch_bounds__(K2_THREADS)
void k2_loop(const float* __restrict__ mw_in,
             const float* __restrict__ al_in,
             const float* __restrict__ pi,
             const float* __restrict__ tau_0,
             const float* __restrict__ tau_p,
             float* __restrict__ out)
{
    const int tid  = threadIdx.x;
    const int b    = blockIdx.x;
    const int wid  = tid >> 5;
    const int lane = tid & 31;

    float* out_mw = out;
    float* out_al = out + OUT_AL_OFF;

    __shared__ float s_mzz[ZDIM * ZDIM];
    __shared__ float2 s_c[NSTEPS];           // per-step (u_var, C2)
    __shared__ float2 s_red[K2_WARPS];
    __shared__ float s_ms[2];

    if (tid < ZDIM * ZDIM) s_mzz[tid] = g_mzz[tid];
    const float tau = tau_p[0];

    const int p0 = b * (K2_THREADS * 2) + tid;     // max 49663 < PDIM
    const int p1 = p0 + K2_THREADS;
    const bool v1 = (p1 < PDIM);

    // Per-thread register state: W columns, ZtR columns, log(pi) for its two p's.
    float W[ZDIM][2], Zt[ZDIM][2], lpi[ZDIM][2];
#pragma unroll
    for (int k = 0; k < ZDIM; k++) {
        {
            float zt = 0.f;
#pragma unroll
            for (int c = 0; c < NSPLIT; c++) zt += g_ztrp[c][k][p0];
            float w = 0.f;
#pragma unroll
            for (int l = 0; l < LDIM; l++) {
                size_t idx = (size_t)(l * ZDIM + k) * PDIM + p0;
                w = fmaf(mw_in[idx], al_in[idx], w);
            }
            Zt[k][0] = zt; W[k][0] = w;
            lpi[k][0] = __logf(pi[(size_t)k * PDIM + p0]);
        }
        if (v1) {
            float zt = 0.f;
#pragma unroll
            for (int c = 0; c < NSPLIT; c++) zt += g_ztrp[c][k][p1];
            float w = 0.f;
#pragma unroll
            for (int l = 0; l < LDIM; l++) {
                size_t idx = (size_t)(l * ZDIM + k) * PDIM + p1;
                w = fmaf(mw_in[idx], al_in[idx], w);
            }
            Zt[k][1] = zt; W[k][1] = w;
            lpi[k][1] = __logf(pi[(size_t)k * PDIM + p1]);
        } else { Zt[k][1] = 0.f; W[k][1] = 0.f; lpi[k][1] = 0.f; }
    }

    // Per-step constants hoisted off the step critical path:
    // u_var = 1/(tau*Ezz + t0);  C2 = 0.5*(tau/Ezz)*(s0inv/(s2+s0inv))
    if (tid < NSTEPS) {
        int k = tid / LDIM, l = tid % LDIM;
        float Ezz  = g_mzz[k * ZDIM + k];
        float t0   = tau_0[l * ZDIM + k];
        float uv   = 1.f / (tau * Ezz + t0);
        float s2   = 1.f / (Ezz * tau);
        float s0i  = 1.f / t0;
        float C2   = 0.5f * (tau / Ezz) * (s0i / (s2 + s0i));
        s_c[k * LDIM + l] = make_float2(uv, C2);
    }
    __syncthreads();

#pragma unroll
    for (int k = 0; k < ZDIM; k++) {
        const float Ezz = s_mzz[k * ZDIM + k];
        float Rt[2], Wk[2];
#pragma unroll
        for (int e = 0; e < 2; e++) {
            float s = Zt[k][e];
#pragma unroll
            for (int j = 0; j < ZDIM; j++)
                s -= s_mzz[k * ZDIM + j] * W[j][e];
            Rt[e] = s + Ezz * W[k][e];            // = ZtR[k] - sum_{j!=k} mzz[k,j]*W[j]
            Wk[e] = W[k][e];
        }

        // preload mw*al products for l=0 of this k
        float pw0, pw1;
        {
            size_t idx = (size_t)k * PDIM + p0;
            pw0 = mw_in[idx] * al_in[idx];
            pw1 = v1 ? mw_in[idx + K2_THREADS] * al_in[idx + K2_THREADS] : 0.f;
        }

        for (int l = 0; l < LDIM; l++) {
            const int step = k * LDIM + l;

            // issue raw loads for next l early (consumed at loop end)
            const int ln = (l + 1 < LDIM) ? l + 1 : l;
            const size_t nidx = (size_t)(ln * ZDIM + k) * PDIM + p0;
            float nm0 = mw_in[nidx], na0 = al_in[nidx];
            float nm1 = 0.f, na1 = 0.f;
            if (v1) { nm1 = mw_in[nidx + K2_THREADS]; na1 = al_in[nidx + K2_THREADS]; }

            const float2 uc    = s_c[step];
            const float u_var  = uc.x;
            const float C2     = uc.y;

            float Wkl0 = Wk[0] - pw0;
            float r0   = Rt[0] - Ezz * Wkl0;
            float lg0  = fmaf(C2 * r0, r0, lpi[k][0]);
            float Wkl1, r1, lg1;
            if (v1) {
                Wkl1 = Wk[1] - pw1;
                r1   = Rt[1] - Ezz * Wkl1;
                lg1  = fmaf(C2 * r1, r1, lpi[k][1]);
            } else { Wkl1 = 0.f; r1 = 0.f; lg1 = -1e30f; }

            // ---- warp-level online softmax reduce (m, s) ----
            float m = fmaxf(lg0, lg1);
            float s = __expf(lg0 - m) + __expf(lg1 - m);
#pragma unroll
            for (int o = 16; o > 0; o >>= 1) {
                float mo = __shfl_xor_sync(0xffffffffu, m, o);
                float so = __shfl_xor_sync(0xffffffffu, s, o);
                comb(m, s, mo, so);
            }
            if (lane == 0) s_red[wid] = make_float2(m, s);
            __syncthreads();

            if (wid == 0) {
                // block-level reduce over 16 warp results (lanes >= 16 neutral)
                float2 wv = (lane < K2_WARPS) ? s_red[lane] : make_float2(-1e30f, 0.f);
                float mb = wv.x, sb = wv.y;
#pragma unroll
                for (int o = 8; o > 0; o >>= 1) {
                    float mo = __shfl_xor_sync(0xffffffffu, mb, o);
                    float so = __shfl_xor_sync(0xffffffffu, sb, o);
                    comb(mb, sb, mo, so);
                }
                if (lane == 0) {
                    publish(&g_part[step][b], &g_cnt[step], mb, sb);
                    // single acquire point: lane0 polls the per-step counter
                    while (ld_acquire_u32(&g_cnt[step]) < K2_BLOCKS) { }
                }
                __syncwarp();

                // ---- grid combine: 2 parallel .cg reads/lane, then shuffles ----
                float2 v0 = __ldcg(&g_part[step][lane]);
                float2 v1g = (lane + 32 < K2_BLOCKS) ? __ldcg(&g_part[step][lane + 32])
                                                     : make_float2(-1e30f, 0.f);
                float ma = v0.x, sa = v0.y;
                comb(ma, sa, v1g.x, v1g.y);
#pragma unroll
                for (int o = 16; o > 0; o >>= 1) {
                    float mo = __shfl_xor_sync(0xffffffffu, ma, o);
                    float so = __shfl_xor_sync(0xffffffffu, sa, o);
                    comb(ma, sa, mo, so);
                }
                if (lane == 0) { s_ms[0] = ma; s_ms[1] = sa; }
            }
            __syncthreads();
            const float gm = s_ms[0];
            const float gs = s_ms[1];

            // ---- normalize, update Wk, store outputs ----
            {
                float a  = __expf(lg0 - gm) / gs;
                float um = tau * u_var * r0;
                Wk[0] = Wkl0 + um * a;
                size_t idx = (size_t)(l * ZDIM + k) * PDIM + p0;
                out_mw[idx] = um;
                out_al[idx] = a;
            }
            if (v1) {
                float a  = __expf(lg1 - gm) / gs;
                float um = tau * u_var * r1;
                Wk[1] = Wkl1 + um * a;
                size_t idx = (size_t)(l * ZDIM + k) * PDIM + p1;
                out_mw[idx] = um;
                out_al[idx] = a;
            }

            // rotate prefetched products into place for next l
            pw0 = nm0 * na0;
            pw1 = nm1 * na1;
        }
        W[k][0] = Wk[0];
        W[k][1] = Wk[1];
    }
}

// ---------------------------------------------------------------------------
extern "C" void kernel_launch(void* const* d_in, const int* in_sizes, int n_in,
                              void* d_out, int out_size)
{
    (void)in_sizes; (void)n_in; (void)out_size;
    const float* data   = (const float*)d_in[0];
    const float* mean_z = (const float*)d_in[1];
    const float* var_z  = (const float*)d_in[2];
    const float* mean_w = (const float*)d_in[3];
    // d_in[4] = var_w (unused: vw output fully overwritten)
    const float* alpha  = (const float*)d_in[5];
    const float* tau_0  = (const float*)d_in[6];
    const float* pi     = (const float*)d_in[7];
    const float* tau    = (const float*)d_in[8];
    float* out = (float*)d_out;

    k1_ztr<<<K1_MAIN + 1, K1_THREADS>>>(data, mean_z, var_z, tau_0, tau,
                                        out + OUT_VW_OFF);
    k2_loop<<<K2_BLOCKS, K2_THREADS>>>(mean_w, alpha, pi, tau_0, tau, out);
}

// round 8
// speedup vs baseline: 1.7777x; 1.1220x over previous
#include <cuda_runtime.h>

#define NDIM 1000
#define PDIM 50000
#define ZDIM 10
#define LDIM 5

#define NSPLIT 8
#define NCHUNK (NDIM / NSPLIT)                        // 125
#define K1_THREADS 256
#define K1_PTILE (K1_THREADS * 4)                     // 1024
#define K1_PTILES ((PDIM + K1_PTILE - 1) / K1_PTILE)  // 49
#define K1_MAIN (K1_PTILES * NSPLIT)                  // 392

#define K2_BLOCKS 49
#define K2_THREADS 512
#define K2_WARPS (K2_THREADS / 32)                    // 16
#define NSTEPS (ZDIM * LDIM)                          // 50

#define OUT_VW_OFF (LDIM * ZDIM * PDIM)               // 250000
#define OUT_AL_OFF (OUT_VW_OFF + LDIM * ZDIM)         // 250050

// Static device scratch (no runtime allocation allowed)
__device__ __align__(16) float g_ztrp[NSPLIT][ZDIM][PDIM];   // 16 MB partials
__device__ float g_mzz[ZDIM * ZDIM];
__device__ __align__(128) float2 g_part[NSTEPS][64];         // per-step (m, s) per block
__device__ int g_cnt[NSTEPS];                                // per-step arrival counters

// ---- R3-proven rendezvous primitives ----
__device__ __forceinline__ void publish(float2* slot, int* cnt, float m, float s) {
    asm volatile("st.global.v2.f32 [%0], {%1, %2};" :: "l"(slot), "f"(m), "f"(s) : "memory");
    // release-ordering: the v2 store is visible at gpu scope before the increment
    asm volatile("red.release.gpu.global.add.u32 [%0], 1;" :: "l"(cnt) : "memory");
}
__device__ __forceinline__ unsigned ld_acquire_u32(const int* p) {
    unsigned v;
    asm volatile("ld.acquire.gpu.global.u32 %0, [%1];" : "=r"(v) : "l"(p) : "memory");
    return v;
}

// one-exp online-softmax combine: (m,s) <- comb((m,s),(mo,so))
// nm = max(m,mo); one rescale factor is always exp(0)=1.
__device__ __forceinline__ void comb(float& m, float& s, float mo, float so) {
    float d = m - mo;
    float e = __expf(-fabsf(d));
    bool ge = (d >= 0.f);
    s = ge ? fmaf(so, e, s) : fmaf(s, e, so);
    m = ge ? m : mo;
}

// ---------------------------------------------------------------------------
// Kernel 1: ZtR partials (ZtR[k,p] = sum_n mean_z[n,k]*data[n,p]) split over
// NSPLIT n-chunks, plus mean_zz, vw output, and counter reset.
// (R3-proven configuration: unroll 2, 256 threads — register-pressure cliff
//  above this; unroll 4 cost ~25us in R7.)
// ---------------------------------------------------------------------------
__global__ __launch_bounds__(K1_THREADS)
void k1_ztr(const float* __restrict__ data,
            const float* __restrict__ mean_z,
            const float* __restrict__ var_z,
            const float* __restrict__ tau_0,
            const float* __restrict__ tau_p,
            float* __restrict__ out_vw)
{
    const int b = blockIdx.x;
    const int tid = threadIdx.x;

    if (b == K1_MAIN) {
        // Aux block: reset counters, compute mean_zz = Z^T Z + N*var_z, write vw.
        if (tid < NSTEPS) g_cnt[tid] = 0;
        __shared__ float s_mzz[ZDIM * ZDIM];
        if (tid < ZDIM * ZDIM) {
            int i = tid / ZDIM, j = tid % ZDIM;
            float s = 0.f;
            for (int n = 0; n < NDIM; n++)
                s += mean_z[n * ZDIM + i] * mean_z[n * ZDIM + j];
            s += (float)NDIM * var_z[i * ZDIM + j];
            s_mzz[tid] = s;
            g_mzz[tid] = s;
        }
        __syncthreads();
        if (tid < LDIM * ZDIM) {
            int l = tid / ZDIM, k = tid % ZDIM;
            float tau = tau_p[0];
            out_vw[tid] = 1.0f / (tau * s_mzz[k * ZDIM + k] + tau_0[l * ZDIM + k]);
        }
        return;
    }

    const int pt = b % K1_PTILES;
    const int c  = b / K1_PTILES;

    // mean_z chunk in shared, rows padded to 12 floats for float4 reads.
    __shared__ __align__(16) float s_z[NCHUNK][12];
    for (int i = tid; i < NCHUNK * ZDIM; i += K1_THREADS) {
        int n = i / ZDIM, kk = i % ZDIM;
        s_z[n][kk] = mean_z[(c * NCHUNK + n) * ZDIM + kk];
    }
    __syncthreads();

    const int p0 = pt * K1_PTILE + tid * 4;
    if (p0 >= PDIM) return;   // P % 4 == 0 -> p0..p0+3 all valid when p0 < P

    float4 acc[ZDIM];
#pragma unroll
    for (int k = 0; k < ZDIM; k++) acc[k] = make_float4(0.f, 0.f, 0.f, 0.f);

    const float* dptr = data + (size_t)c * NCHUNK * PDIM + p0;
#pragma unroll 2
    for (int n = 0; n < NCHUNK; n++) {
        float4 d = *reinterpret_cast<const float4*>(dptr + (size_t)n * PDIM);
        const float4* zr = reinterpret_cast<const float4*>(s_z[n]);
        float4 z0 = zr[0], z1 = zr[1], z2 = zr[2];
        float zk[ZDIM] = {z0.x, z0.y, z0.z, z0.w, z1.x, z1.y, z1.z, z1.w, z2.x, z2.y};
#pragma unroll
        for (int k = 0; k < ZDIM; k++) {
            acc[k].x = fmaf(zk[k], d.x, acc[k].x);
            acc[k].y = fmaf(zk[k], d.y, acc[k].y);
            acc[k].z = fmaf(zk[k], d.z, acc[k].z);
            acc[k].w = fmaf(zk[k], d.w, acc[k].w);
        }
    }
#pragma unroll
    for (int k = 0; k < ZDIM; k++)
        *reinterpret_cast<float4*>(&g_ztrp[c][k][p0]) = acc[k];
}

// ---------------------------------------------------------------------------
// Kernel 2: persistent serial coordinate-descent sweep. 49 co-resident CTAs
// of 512 threads, each thread owns 2 p-columns. R3-shape rendezvous: counter
// RED + lane0 acquire-poll + parallel .cg partial reads. Softmax numerators
// precomputed pre-barrier (off the post-broadcast critical path).
// ---------------------------------------------------------------------------
__global__ __launch_bounds__(K2_THREADS)
void k2_loop(const float* __restrict__ mw_in,
             const float* __restrict__ al_in,
             const float* __restrict__ pi,
             const float* __restrict__ tau_0,
             const float* __restrict__ tau_p,
             float* __restrict__ out)
{
    const int tid  = threadIdx.x;
    const int b    = blockIdx.x;
    const int wid  = tid >> 5;
    const int lane = tid & 31;

    float* out_mw = out;
    float* out_al = out + OUT_AL_OFF;

    __shared__ float s_mzz[ZDIM * ZDIM];
    __shared__ float2 s_c[NSTEPS];           // per-step (u_var, C2)
    __shared__ float2 s_red[K2_WARPS];
    __shared__ float s_ms[2];

    if (tid < ZDIM * ZDIM) s_mzz[tid] = g_mzz[tid];
    const float tau = tau_p[0];

    const int p0 = b * (K2_THREADS * 2) + tid;     // max 49663 < PDIM
    const int p1 = p0 + K2_THREADS;
    const bool v1 = (p1 < PDIM);

    // Per-thread register state: W columns, ZtR columns, log(pi) for its two p's.
    float W[ZDIM][2], Zt[ZDIM][2], lpi[ZDIM][2];
#pragma unroll
    for (int k = 0; k < ZDIM; k++) {
        {
            float zt = 0.f;
#pragma unroll
            for (int c = 0; c < NSPLIT; c++) zt += g_ztrp[c][k][p0];
            float w = 0.f;
#pragma unroll
            for (int l = 0; l < LDIM; l++) {
                size_t idx = (size_t)(l * ZDIM + k) * PDIM + p0;
                w = fmaf(mw_in[idx], al_in[idx], w);
            }
            Zt[k][0] = zt; W[k][0] = w;
            lpi[k][0] = __logf(pi[(size_t)k * PDIM + p0]);
        }
        if (v1) {
            float zt = 0.f;
#pragma unroll
            for (int c = 0; c < NSPLIT; c++) zt += g_ztrp[c][k][p1];
            float w = 0.f;
#pragma unroll
            for (int l = 0; l < LDIM; l++) {
                size_t idx = (size_t)(l * ZDIM + k) * PDIM + p1;
                w = fmaf(mw_in[idx], al_in[idx], w);
            }
            Zt[k][1] = zt; W[k][1] = w;
            lpi[k][1] = __logf(pi[(size_t)k * PDIM + p1]);
        } else { Zt[k][1] = 0.f; W[k][1] = 0.f; lpi[k][1] = 0.f; }
    }

    // Per-step constants hoisted off the step critical path:
    if (tid < NSTEPS) {
        int k = tid / LDIM, l = tid % LDIM;
        float Ezz  = g_mzz[k * ZDIM + k];
        float t0   = tau_0[l * ZDIM + k];
        float uv   = 1.f / (tau * Ezz + t0);
        float s2   = 1.f / (Ezz * tau);
        float s0i  = 1.f / t0;
        float C2   = 0.5f * (tau / Ezz) * (s0i / (s2 + s0i));
        s_c[k * LDIM + l] = make_float2(uv, C2);
    }
    __syncthreads();

#pragma unroll
    for (int k = 0; k < ZDIM; k++) {
        const float Ezz = s_mzz[k * ZDIM + k];
        float Rt[2], Wk[2];
#pragma unroll
        for (int e = 0; e < 2; e++) {
            float s = Zt[k][e];
#pragma unroll
            for (int j = 0; j < ZDIM; j++)
                s -= s_mzz[k * ZDIM + j] * W[j][e];
            Rt[e] = s + Ezz * W[k][e];            // = ZtR[k] - sum_{j!=k} mzz[k,j]*W[j]
            Wk[e] = W[k][e];
        }

        // preload mw*al products for l=0 of this k
        float pw0, pw1;
        {
            size_t idx = (size_t)k * PDIM + p0;
            pw0 = mw_in[idx] * al_in[idx];
            pw1 = v1 ? mw_in[idx + K2_THREADS] * al_in[idx + K2_THREADS] : 0.f;
        }

        for (int l = 0; l < LDIM; l++) {
            const int step = k * LDIM + l;

            // issue raw loads for next l early (consumed at loop end)
            const int ln = (l + 1 < LDIM) ? l + 1 : l;
            const size_t nidx = (size_t)(ln * ZDIM + k) * PDIM + p0;
            float nm0 = mw_in[nidx], na0 = al_in[nidx];
            float nm1 = 0.f, na1 = 0.f;
            if (v1) { nm1 = mw_in[nidx + K2_THREADS]; na1 = al_in[nidx + K2_THREADS]; }

            const float2 uc    = s_c[step];
            const float u_var  = uc.x;
            const float C2     = uc.y;

            float Wkl0 = Wk[0] - pw0;
            float r0   = Rt[0] - Ezz * Wkl0;
            float lg0  = fmaf(C2 * r0, r0, lpi[k][0]);
            float Wkl1, r1, lg1;
            if (v1) {
                Wkl1 = Wk[1] - pw1;
                r1   = Rt[1] - Ezz * Wkl1;
                lg1  = fmaf(C2 * r1, r1, lpi[k][1]);
            } else { Wkl1 = 0.f; r1 = 0.f; lg1 = -1e30f; }

            // ---- warp-level online softmax reduce (m, s) ----
            float m = fmaxf(lg0, lg1);
            float s = __expf(lg0 - m) + __expf(lg1 - m);
#pragma unroll
            for (int o = 16; o > 0; o >>= 1) {
                float mo = __shfl_xor_sync(0xffffffffu, m, o);
                float so = __shfl_xor_sync(0xffffffffu, s, o);
                comb(m, s, mo, so);
            }
            // pre-barrier: per-thread softmax numerators vs the warp max
            // (off the post-broadcast critical path; a = e * exp(m-gm)/gs later)
            const float e0 = __expf(lg0 - m);
            const float e1 = v1 ? __expf(lg1 - m) : 0.f;

            if (lane == 0) s_red[wid] = make_float2(m, s);
            __syncthreads();

            if (wid == 0) {
                // block-level reduce over 16 warp results (lanes >= 16 neutral)
                float2 wv = (lane < K2_WARPS) ? s_red[lane] : make_float2(-1e30f, 0.f);
                float mb = wv.x, sb = wv.y;
#pragma unroll
                for (int o = 8; o > 0; o >>= 1) {
                    float mo = __shfl_xor_sync(0xffffffffu, mb, o);
                    float so = __shfl_xor_sync(0xffffffffu, sb, o);
                    comb(mb, sb, mo, so);
                }
                if (lane == 0) {
                    publish(&g_part[step][b], &g_cnt[step], mb, sb);
                    // single acquire point: lane0 polls the per-step counter
                    while (ld_acquire_u32(&g_cnt[step]) < K2_BLOCKS) { }
                }
                __syncwarp();

                // ---- grid combine: 2 parallel .cg reads/lane, then shuffles ----
                float2 v0 = __ldcg(&g_part[step][lane]);
                float2 v1g = (lane + 32 < K2_BLOCKS) ? __ldcg(&g_part[step][lane + 32])
                                                     : make_float2(-1e30f, 0.f);
                float ma = v0.x, sa = v0.y;
                comb(ma, sa, v1g.x, v1g.y);
#pragma unroll
                for (int o = 16; o > 0; o >>= 1) {
                    float mo = __shfl_xor_sync(0xffffffffu, ma, o);
                    float so = __shfl_xor_sync(0xffffffffu, sa, o);
                    comb(ma, sa, mo, so);
                }
                if (lane == 0) { s_ms[0] = ma; s_ms[1] = sa; }
            }
            __syncthreads();
            const float gm = s_ms[0];
            const float gs = s_ms[1];

            // ---- normalize via precomputed numerators, update Wk, store ----
            // a = exp(lg - gm)/gs = e * exp(m - gm) / gs ; one exp + one rcp
            const float corr = __expf(m - gm) * __frcp_rn(gs);
            {
                float a  = e0 * corr;
                float um = tau * u_var * r0;
                Wk[0] = Wkl0 + um * a;
                size_t idx = (size_t)(l * ZDIM + k) * PDIM + p0;
                out_mw[idx] = um;
                out_al[idx] = a;
            }
            if (v1) {
                float a  = e1 * corr;
                float um = tau * u_var * r1;
                Wk[1] = Wkl1 + um * a;
                size_t idx = (size_t)(l * ZDIM + k) * PDIM + p1;
                out_mw[idx] = um;
                out_al[idx] = a;
            }

            // rotate prefetched products into place for next l
            pw0 = nm0 * na0;
            pw1 = nm1 * na1;
        }
        W[k][0] = Wk[0];
        W[k][1] = Wk[1];
    }
}

// ---------------------------------------------------------------------------
extern "C" void kernel_launch(void* const* d_in, const int* in_sizes, int n_in,
                              void* d_out, int out_size)
{
    (void)in_sizes; (void)n_in; (void)out_size;
    const float* data   = (const float*)d_in[0];
    const float* mean_z = (const float*)d_in[1];
    const float* var_z  = (const float*)d_in[2];
    const float* mean_w = (const float*)d_in[3];
    // d_in[4] = var_w (unused: vw output fully overwritten)
    const float* alpha  = (const float*)d_in[5];
    const float* tau_0  = (const float*)d_in[6];
    const float* pi     = (const float*)d_in[7];
    const float* tau    = (const float*)d_in[8];
    float* out = (float*)d_out;

    k1_ztr<<<K1_MAIN + 1, K1_THREADS>>>(data, mean_z, var_z, tau_0, tau,
                                        out + OUT_VW_OFF);
    k2_loop<<<K2_BLOCKS, K2_THREADS>>>(mean_w, alpha, pi, tau_0, tau, out);
}